// round 1
// baseline (speedup 1.0000x reference)
#include <cuda_runtime.h>
#include <cuda_bf16.h>

// Problem constants (dataset is fixed: 50000 nodes, 800000 edges, 64 feats)
#define MAX_NODES 50048
#define MAX_EDGES 800000
#define SCAN_BLK  1024
#define MAX_SCAN_BLOCKS 64   // ceil(50000/1024) = 49

// Scratch (allocation-free rule: __device__ globals)
__device__ int g_count[MAX_NODES];
__device__ int g_offset[MAX_NODES + 1];
__device__ int g_cursor[MAX_NODES];
__device__ int g_srow[MAX_EDGES];
__device__ int g_blocksum[MAX_SCAN_BLOCKS];
__device__ int g_blockbase[MAX_SCAN_BLOCKS];

__global__ void k_zero(int n) {
    int i = blockIdx.x * blockDim.x + threadIdx.x;
    if (i < n) g_count[i] = 0;
}

__global__ void k_hist(const int* __restrict__ col, int E) {
    int i = blockIdx.x * blockDim.x + threadIdx.x;
    if (i < E) atomicAdd(&g_count[col[i]], 1);
}

// Block-level partial sums of g_count
__global__ void k_scanA(int n) {
    __shared__ int sh[SCAN_BLK];
    int i = blockIdx.x * SCAN_BLK + threadIdx.x;
    int v = (i < n) ? g_count[i] : 0;
    sh[threadIdx.x] = v;
    __syncthreads();
    for (int s = SCAN_BLK / 2; s > 0; s >>= 1) {
        if (threadIdx.x < s) sh[threadIdx.x] += sh[threadIdx.x + s];
        __syncthreads();
    }
    if (threadIdx.x == 0) g_blocksum[blockIdx.x] = sh[0];
}

// Exclusive scan of the (<=64) block sums; also writes offset[n] = total edges
__global__ void k_scanB(int nblocks, int n) {
    __shared__ int sh[MAX_SCAN_BLOCKS];
    int t = threadIdx.x;
    int v = (t < nblocks) ? g_blocksum[t] : 0;
    sh[t] = v;
    __syncthreads();
    #pragma unroll
    for (int s = 1; s < MAX_SCAN_BLOCKS; s <<= 1) {
        int a = (t >= s) ? sh[t - s] : 0;
        __syncthreads();
        sh[t] += a;
        __syncthreads();
    }
    if (t < nblocks) g_blockbase[t] = sh[t] - v;      // exclusive base
    if (t == MAX_SCAN_BLOCKS - 1) g_offset[n] = sh[t]; // total
}

// Intra-block exclusive scan + global base -> CSR offsets (and cursor copy)
__global__ void k_scanC(int n) {
    __shared__ int sh[SCAN_BLK];
    int i = blockIdx.x * SCAN_BLK + threadIdx.x;
    int v = (i < n) ? g_count[i] : 0;
    sh[threadIdx.x] = v;
    __syncthreads();
    for (int s = 1; s < SCAN_BLK; s <<= 1) {
        int a = (threadIdx.x >= (unsigned)s) ? sh[threadIdx.x - s] : 0;
        __syncthreads();
        sh[threadIdx.x] += a;
        __syncthreads();
    }
    if (i < n) {
        int excl = g_blockbase[blockIdx.x] + sh[threadIdx.x] - v;
        g_offset[i] = excl;
        g_cursor[i] = excl;
    }
}

// Bucket the source node of every edge by destination (counting sort)
__global__ void k_scatter(const int* __restrict__ row, const int* __restrict__ col, int E) {
    int i = blockIdx.x * blockDim.x + threadIdx.x;
    if (i < E) {
        int c = col[i];
        int pos = atomicAdd(&g_cursor[c], 1);
        g_srow[pos] = row[i];
    }
}

// One warp per destination node; lane handles features [2*lane, 2*lane+1].
// Atomic-free segmented mean; gathers are L2-resident.
__global__ void k_gather(const float* __restrict__ x, float* __restrict__ out, int n) {
    int warp = (blockIdx.x * blockDim.x + threadIdx.x) >> 5;
    int lane = threadIdx.x & 31;
    if (warp >= n) return;
    int start = g_offset[warp];
    int end   = g_offset[warp + 1];

    float2 a0 = make_float2(0.f, 0.f);
    float2 a1 = make_float2(0.f, 0.f);
    int i = start;
    // 2-way unroll with independent accumulators for MLP
    for (; i + 2 <= end; i += 2) {
        int r0 = g_srow[i];
        int r1 = g_srow[i + 1];
        float2 v0 = *reinterpret_cast<const float2*>(x + ((size_t)r0 << 6) + (lane << 1));
        float2 v1 = *reinterpret_cast<const float2*>(x + ((size_t)r1 << 6) + (lane << 1));
        a0.x += v0.x; a0.y += v0.y;
        a1.x += v1.x; a1.y += v1.y;
    }
    if (i < end) {
        int r0 = g_srow[i];
        float2 v0 = *reinterpret_cast<const float2*>(x + ((size_t)r0 << 6) + (lane << 1));
        a0.x += v0.x; a0.y += v0.y;
    }
    int deg = end - start;
    float inv = 1.0f / (float)(deg > 0 ? deg : 1);
    float2 o = make_float2((a0.x + a1.x) * inv, (a0.y + a1.y) * inv);
    *reinterpret_cast<float2*>(out + ((size_t)warp << 6) + (lane << 1)) = o;
}

extern "C" void kernel_launch(void* const* d_in, const int* in_sizes, int n_in,
                              void* d_out, int out_size) {
    const float* x    = (const float*)d_in[0];
    const int*   edge = (const int*)d_in[1];
    float*       out  = (float*)d_out;

    const int n = in_sizes[0] / 64;     // 50000
    const int E = in_sizes[1] / 2;      // 800000
    const int* row = edge;              // edge_index[0, :]
    const int* col = edge + E;          // edge_index[1, :]

    const int nb_scan = (n + SCAN_BLK - 1) / SCAN_BLK;   // 49

    k_zero   <<<(n + 255) / 256, 256>>>(n);
    k_hist   <<<(E + 255) / 256, 256>>>(col, E);
    k_scanA  <<<nb_scan, SCAN_BLK>>>(n);
    k_scanB  <<<1, MAX_SCAN_BLOCKS>>>(nb_scan, n);
    k_scanC  <<<nb_scan, SCAN_BLK>>>(n);
    k_scatter<<<(E + 255) / 256, 256>>>(row, col, E);
    // 8 warps per block, one warp per node
    k_gather <<<(n + 7) / 8, 256>>>(x, out, n);
}